// round 1
// baseline (speedup 1.0000x reference)
#include <cuda_runtime.h>
#include <cfloat>
#include <math.h>

// ---------------------------------------------------------------------------
// VectorQuantizer: z (32,2048,256) f32, emb (1024,256) f32
// Outputs (flattened, float32, in tuple order):
//   [0]                       loss
//   [1 .. 1+16777216)         z_q  (straight-through: z + (e - z))
//   [16777217]                perplexity
//   [16777218 .. +67108864)   min_encodings (one-hot, f32)
//   [83886082 .. +65536)      min_encoding_indices (as float)
// ---------------------------------------------------------------------------

#define NROWS   65536
#define CDIM    256
#define NE      1024

#define OFF_LOSS 0LL
#define OFF_ZQ   1LL
#define OFF_PERP 16777217LL
#define OFF_ENC  16777218LL
#define OFF_IDX  83886082LL

// ----- device scratch (no allocations allowed) -----
__device__ float g_enorm[NE];
__device__ int   g_idx[NROWS];
__device__ float g_part[2048];
__device__ int   g_counts[NE];

// ----- packed f32x2 helpers (Blackwell FFMA2) -----
__device__ __forceinline__ void ffma2(unsigned long long& d,
                                      unsigned long long a,
                                      unsigned long long b) {
    asm("fma.rn.f32x2 %0, %1, %2, %0;" : "+l"(d) : "l"(a), "l"(b));
}
__device__ __forceinline__ float2 unpack2(unsigned long long x) {
    float2 f;
    asm("mov.b64 {%0, %1}, %2;" : "=f"(f.x), "=f"(f.y) : "l"(x));
    return f;
}

// ---------------------------------------------------------------------------
// Kernel 0: zero the histogram (replayed every launch for determinism)
// ---------------------------------------------------------------------------
__global__ void vq_init() {
    g_counts[threadIdx.x] = 0;
}

// ---------------------------------------------------------------------------
// Kernel 1: ||e_j||^2 per code (one warp per code)
// ---------------------------------------------------------------------------
__global__ void vq_enorm(const float* __restrict__ emb) {
    int gw   = (blockIdx.x * blockDim.x + threadIdx.x) >> 5;
    int lane = threadIdx.x & 31;
    if (gw >= NE) return;
    const float* e = emb + (size_t)gw * CDIM;
    float s = 0.f;
    #pragma unroll
    for (int i = lane; i < CDIM; i += 32) { float x = e[i]; s += x * x; }
    #pragma unroll
    for (int o = 16; o > 0; o >>= 1) s += __shfl_down_sync(0xffffffffu, s, o);
    if (lane == 0) g_enorm[gw] = s;
}

// ---------------------------------------------------------------------------
// Kernel 2: main distance + argmin.
//   CTA: 128 rows x all 1024 codes (16 code-tiles of 64), 256 threads (16x16).
//   Thread micro-tile: 8 rows x 4 codes, packed f32x2 over k-pairs.
//   smem: zs[128][260] + es[64][260] + enorm[1024] + znorm[128] = 204288 B.
//   Score replicates reference rounding: s = fl(fl(zn + en_j) - 2*dot).
// ---------------------------------------------------------------------------
#define ZS_STRIDE 260
#define SMEM_MAIN ((128 * ZS_STRIDE + 64 * ZS_STRIDE + NE + 128) * 4)

__global__ void __launch_bounds__(256, 1)
vq_main(const float* __restrict__ z, const float* __restrict__ emb,
        float* __restrict__ out) {
    extern __shared__ float smem[];
    float* zs      = smem;                        // [128][260]
    float* es      = smem + 128 * ZS_STRIDE;      // [64][260]
    float* enorm_s = es + 64 * ZS_STRIDE;         // [1024]
    float* znorm_s = enorm_s + NE;                // [128]

    const int tid = threadIdx.x;
    const int tx  = tid & 15;          // code dim
    const int ty  = tid >> 4;          // row dim
    const int r0  = ty * 8;
    const int rowBase = blockIdx.x * 128;

    // ---- load z tile (coalesced float4), row-major padded ----
    {
        const float4* zg = (const float4*)z;
        #pragma unroll
        for (int i = tid; i < 128 * 64; i += 256) {
            int row = i >> 6, k4 = i & 63;
            float4 v = zg[(size_t)(rowBase + row) * 64 + k4];
            *(float4*)&zs[row * ZS_STRIDE + k4 * 4] = v;
        }
    }
    // ---- load code norms ----
    for (int i = tid; i < NE; i += 256) enorm_s[i] = g_enorm[i];
    __syncthreads();

    // ---- per-row ||z||^2 (square then add, plain fp32) ----
    if (tid < 128) {
        const float* zr = &zs[tid * ZS_STRIDE];
        float s = 0.f;
        for (int c = 0; c < CDIM; ++c) { float x = zr[c]; s += x * x; }
        znorm_s[tid] = s;
    }
    __syncthreads();

    float zn[8];
    #pragma unroll
    for (int v = 0; v < 8; ++v) zn[v] = znorm_s[r0 + v];

    float bv[8]; int bi[8];
    #pragma unroll
    for (int v = 0; v < 8; ++v) { bv[v] = FLT_MAX; bi[v] = 0; }

    for (int ct = 0; ct < 16; ++ct) {
        __syncthreads();
        // load 64-code tile of emb
        {
            const float4* eg = (const float4*)emb;
            #pragma unroll
            for (int i = tid; i < 64 * 64; i += 256) {
                int c = i >> 6, k4 = i & 63;
                float4 v = eg[(size_t)(ct * 64 + c) * 64 + k4];
                *(float4*)&es[c * ZS_STRIDE + k4 * 4] = v;
            }
        }
        __syncthreads();

        unsigned long long acc[8][4];
        #pragma unroll
        for (int v = 0; v < 8; ++v)
            #pragma unroll
            for (int u = 0; u < 4; ++u) acc[v][u] = 0ULL;

        #pragma unroll 2
        for (int k4 = 0; k4 < 64; ++k4) {
            ulonglong2 a[8];
            #pragma unroll
            for (int v = 0; v < 8; ++v)
                a[v] = *(const ulonglong2*)&zs[(r0 + v) * ZS_STRIDE + k4 * 4];
            ulonglong2 b[4];
            #pragma unroll
            for (int u = 0; u < 4; ++u)
                b[u] = *(const ulonglong2*)&es[(u * 16 + tx) * ZS_STRIDE + k4 * 4];
            #pragma unroll
            for (int v = 0; v < 8; ++v)
                #pragma unroll
                for (int u = 0; u < 4; ++u) {
                    ffma2(acc[v][u], a[v].x, b[u].x);
                    ffma2(acc[v][u], a[v].y, b[u].y);
                }
        }

        // score + running argmin (ascending code order; explicit tie->lower idx)
        #pragma unroll
        for (int v = 0; v < 8; ++v)
            #pragma unroll
            for (int u = 0; u < 4; ++u) {
                float2 p = unpack2(acc[v][u]);
                float dot = p.x + p.y;
                int   j   = ct * 64 + u * 16 + tx;
                float t   = zn[v] + enorm_s[j];   // fl(zn + en)
                float s   = t - 2.0f * dot;       // fl(t - 2*dot), 2*dot exact
                if (s < bv[v] || (s == bv[v] && j < bi[v])) { bv[v] = s; bi[v] = j; }
            }
    }

    // ---- cross-thread reduce per row (16 candidates, lowest-index ties) ----
    __syncthreads();
    float* redv = es;                 // reuse es region: 2048 floats
    int*   redi = (int*)(es + 2048);  // 2048 ints
    #pragma unroll
    for (int v = 0; v < 8; ++v) {
        redv[(r0 + v) * 16 + tx] = bv[v];
        redi[(r0 + v) * 16 + tx] = bi[v];
    }
    __syncthreads();
    if (tid < 128) {
        int row = tid;
        float bvv = redv[row * 16];
        int   bii = redi[row * 16];
        #pragma unroll
        for (int j = 1; j < 16; ++j) {
            float v2 = redv[row * 16 + j];
            int   i2 = redi[row * 16 + j];
            if (v2 < bvv || (v2 == bvv && i2 < bii)) { bvv = v2; bii = i2; }
        }
        int grow = rowBase + row;
        g_idx[grow] = bii;
        out[OFF_IDX + grow] = (float)bii;
    }
}

// ---------------------------------------------------------------------------
// Kernel 3: z_q gather + straight-through + loss partials + one-hot scatter
//   + histogram. 2048 blocks x 256 threads, 32 rows/block. Deterministic
//   (fixed-order block tree reduce; integer atomics only for counts).
// ---------------------------------------------------------------------------
__global__ void __launch_bounds__(256)
vq_epilogue(const float* __restrict__ z, const float* __restrict__ emb,
            float* __restrict__ out) {
    __shared__ int   hist[NE];
    __shared__ float rbuf[256];
    int tid = threadIdx.x;
    #pragma unroll
    for (int i = tid; i < NE; i += 256) hist[i] = 0;
    __syncthreads();

    int rowBase = blockIdx.x * 32;
    float psum = 0.f;
    for (int r = 0; r < 32; ++r) {
        int row = rowBase + r;
        int idx = g_idx[row];
        float e  = emb[(size_t)idx * CDIM + tid];
        float zz = z[(size_t)row * CDIM + tid];
        float d  = e - zz;
        out[OFF_ZQ + (long long)row * CDIM + tid] = zz + d;  // z + sg(z_q - z)
        psum += d * d;
    }
    if (tid < 32) {
        int row = rowBase + tid;
        int idx = g_idx[row];
        atomicAdd(&hist[idx], 1);
        out[OFF_ENC + (long long)row * NE + idx] = 1.0f;
    }
    rbuf[tid] = psum;
    __syncthreads();
    #pragma unroll
    for (int s = 128; s > 0; s >>= 1) {
        if (tid < s) rbuf[tid] += rbuf[tid + s];
        __syncthreads();
    }
    if (tid == 0) g_part[blockIdx.x] = rbuf[0];
    #pragma unroll
    for (int i = tid; i < NE; i += 256) {
        int h = hist[i];
        if (h) atomicAdd(&g_counts[i], h);
    }
}

// ---------------------------------------------------------------------------
// Kernel 4: finalize loss + perplexity (deterministic double reductions)
// ---------------------------------------------------------------------------
__global__ void vq_finalize(float* __restrict__ out) {
    __shared__ double sd[256];
    int tid = threadIdx.x;
    double s = 0.0;
    for (int i = tid; i < 2048; i += 256) s += (double)g_part[i];
    sd[tid] = s;
    __syncthreads();
    #pragma unroll
    for (int st = 128; st > 0; st >>= 1) {
        if (tid < st) sd[tid] += sd[tid + st];
        __syncthreads();
    }
    if (tid == 0) {
        double mean = sd[0] / 16777216.0;
        out[OFF_LOSS] = (float)(mean + 0.25 * mean);
    }
    __syncthreads();
    double h = 0.0;
    for (int i = tid; i < NE; i += 256) {
        double m = (double)g_counts[i] / 65536.0;
        h += m * log(m + 1e-10);
    }
    sd[tid] = h;
    __syncthreads();
    #pragma unroll
    for (int st = 128; st > 0; st >>= 1) {
        if (tid < st) sd[tid] += sd[tid + st];
        __syncthreads();
    }
    if (tid == 0) out[OFF_PERP] = (float)exp(-sd[0]);
}

// ---------------------------------------------------------------------------
extern "C" void kernel_launch(void* const* d_in, const int* in_sizes, int n_in,
                              void* d_out, int out_size) {
    const float* z   = (const float*)d_in[0];   // 32*2048*256
    const float* emb = (const float*)d_in[1];   // 1024*256
    float* out = (float*)d_out;

    static int attr_done = 0;
    if (!attr_done) {
        cudaFuncSetAttribute(vq_main, cudaFuncAttributeMaxDynamicSharedMemorySize,
                             SMEM_MAIN);
        attr_done = 1;
    }

    vq_init<<<1, NE>>>();
    vq_enorm<<<128, 256>>>(emb);
    cudaMemsetAsync(out + OFF_ENC, 0, (size_t)NROWS * NE * sizeof(float));
    vq_main<<<NROWS / 128, 256, SMEM_MAIN>>>(z, emb, out);
    vq_epilogue<<<NROWS / 32, 256>>>(z, emb, out);
    vq_finalize<<<1, 256>>>(out);
}

// round 3
// speedup vs baseline: 3.5429x; 3.5429x over previous
#include <cuda_runtime.h>
#include <cuda_bf16.h>
#include <cfloat>
#include <math.h>
#include <stdint.h>

// ---------------------------------------------------------------------------
// VectorQuantizer: z (32,2048,256) f32, emb (1024,256) f32
// Output layout (float32):
//   [0] loss | [1..16777217) z_q | [16777217] perplexity
//   [16777218..+67108864) one-hot | [83886082..+65536) indices
// Strategy: bf16 HMMA (mma.sync m16n8k16) approximate distance matrix,
// top-2/thread candidate lists, exact fp32 rescore of in-margin candidates
// with reference-identical rounding (validated in R1: zero argmin flips).
// ---------------------------------------------------------------------------

#define NROWS   65536
#define CDIM    256
#define NE      1024

#define OFF_LOSS 0LL
#define OFF_ZQ   1LL
#define OFF_PERP 16777217LL
#define OFF_ENC  16777218LL
#define OFF_IDX  83886082LL

#define MARGIN 1.5e-3f

// ----- device scratch -----
__device__ uint4 g_eb4[NE * CDIM / 8];      // emb as bf16 (row-major, 512KB)
__device__ float g_enorm[NE];
__device__ int   g_idx[NROWS];
__device__ float g_part[2048];
__device__ int   g_counts[NE];

// ======================= smem layout (bytes) ===============================
// Rows padded to 528 B (264 bf16): stride mod 128 = 16 -> ldmatrix phases
// conflict-free (8 rows spread banks 4 apart, 16B each -> full 32 banks).
#define RST 528
#define SM_A       0                      // 128*528 = 67584
#define SM_B0      67584                  // 64*528  = 33792
#define SM_B1      101376                 // 33792
#define SM_EN      135168                 // 4096
#define SM_ZN      139264                 // 512
#define SM_CAND    139776                 // 128*16*8 = 16384
#define SM_ROWRES  156160                 // 1024
#define SM_LIST    157184                 // 2048*8 = 16384
#define SM_CNT     173568                 // 16
#define SMEM_TC    173584

// ======================= PTX helpers =======================================
__device__ __forceinline__ uint32_t smem_u32(const void* p) {
    uint32_t a;
    asm("{ .reg .u64 t; cvta.to.shared.u64 t, %1; cvt.u32.u64 %0, t; }"
        : "=r"(a) : "l"(p));
    return a;
}
#define LDSM_X4(r0, r1, r2, r3, addr) \
    asm volatile("ldmatrix.sync.aligned.m8n8.x4.shared.b16 {%0,%1,%2,%3}, [%4];" \
                 : "=r"(r0), "=r"(r1), "=r"(r2), "=r"(r3) : "r"(addr))
#define MMA16816(c0, c1, c2, c3, a0, a1, a2, a3, b0, b1) \
    asm volatile("mma.sync.aligned.m16n8k16.row.col.f32.bf16.bf16.f32 " \
                 "{%0,%1,%2,%3}, {%4,%5,%6,%7}, {%8,%9}, {%0,%1,%2,%3};" \
                 : "+f"(c0), "+f"(c1), "+f"(c2), "+f"(c3) \
                 : "r"(a0), "r"(a1), "r"(a2), "r"(a3), "r"(b0), "r"(b1))
#define CP16(dst, src) \
    asm volatile("cp.async.cg.shared.global [%0], [%1], 16;" :: "r"(dst), "l"(src))
#define CP_COMMIT() asm volatile("cp.async.commit_group;" ::: "memory")
#define CP_WAIT0()  asm volatile("cp.async.wait_group 0;" ::: "memory")

#define INS2(vv, jj, s, j) do {                                   \
    if ((s) < vv[1]) {                                            \
        if ((s) < vv[0]) { vv[1]=vv[0]; jj[1]=jj[0]; vv[0]=(s); jj[0]=(j); } \
        else             { vv[1]=(s); jj[1]=(j); }                \
    } } while (0)

// ---------------------------------------------------------------------------
__global__ void vq_init() { g_counts[threadIdx.x] = 0; }

// ||e_j||^2 — verbatim R1 rounding (validated: zero flips).
__global__ void vq_enorm(const float* __restrict__ emb) {
    int gw   = (blockIdx.x * blockDim.x + threadIdx.x) >> 5;
    int lane = threadIdx.x & 31;
    if (gw >= NE) return;
    const float* e = emb + (size_t)gw * CDIM;
    float s = 0.f;
    #pragma unroll
    for (int i = lane; i < CDIM; i += 32) { float x = e[i]; s += x * x; }
    #pragma unroll
    for (int o = 16; o > 0; o >>= 1) s += __shfl_down_sync(0xffffffffu, s, o);
    if (lane == 0) g_enorm[gw] = s;
}

// emb f32 -> bf16 (row-major)
__global__ void __launch_bounds__(256)
vq_prep_e(const float* __restrict__ emb) {
    int idx = blockIdx.x * 256 + threadIdx.x;        // 0..32767, 8 floats each
    const float4* s4 = (const float4*)emb + idx * 2;
    float4 a = s4[0], b = s4[1];
    __nv_bfloat162 h0 = __floats2bfloat162_rn(a.x, a.y);
    __nv_bfloat162 h1 = __floats2bfloat162_rn(a.z, a.w);
    __nv_bfloat162 h2 = __floats2bfloat162_rn(b.x, b.y);
    __nv_bfloat162 h3 = __floats2bfloat162_rn(b.z, b.w);
    uint4 pk;
    pk.x = *(uint32_t*)&h0; pk.y = *(uint32_t*)&h1;
    pk.z = *(uint32_t*)&h2; pk.w = *(uint32_t*)&h3;
    g_eb4[idx] = pk;
}

// Prefetch one 64-code bf16 tile into smem (padded rows) via cp.async.
__device__ __forceinline__ void prefetch_B(uint32_t sdst, int ct, int tid) {
    const char* gsrc = (const char*)g_eb4 + (size_t)ct * 64 * 512;
    #pragma unroll
    for (int j = 0; j < 8; ++j) {
        int idx = tid + j * 256;              // 0..2047
        int row = idx >> 5, g = idx & 31;
        CP16(sdst + row * RST + g * 16, gsrc + row * 512 + g * 16);
    }
    CP_COMMIT();
}

// ---------------------------------------------------------------------------
// Main kernel: 512 CTAs x 256 threads. CTA = 128 rows x 1024 codes.
// Warps: 4(M) x 2(N); warp tile 32 rows x 32 codes per 64-code smem tile.
// ---------------------------------------------------------------------------
__global__ void __launch_bounds__(256, 1)
vq_main_mma(const float* __restrict__ zf, const float* __restrict__ emb,
            float* __restrict__ out) {
    extern __shared__ char smem[];
    const uint32_t sb = smem_u32(smem);
    const int tid = threadIdx.x;
    const int lane = tid & 31, wid = tid >> 5;
    const int mwarp = wid & 3, nwarp = wid >> 2;
    const int rowBase = blockIdx.x * 128;

    float* ens = (float*)(smem + SM_EN);
    float* zns = (float*)(smem + SM_ZN);
    float* tmp = (float*)(smem + SM_CAND);   // reused before cand phase

    for (int i = tid; i < NE; i += 256) ens[i] = g_enorm[i];

    // ---- A tile: load z f32, convert to bf16 (padded smem), norm partials
    {
        int row = tid >> 1, half = tid & 1;
        const float4* zr = (const float4*)zf + ((size_t)(rowBase + row) * 64 + half * 32);
        char* arow = smem + SM_A + row * RST + half * 256;
        float s = 0.f;
        #pragma unroll
        for (int j = 0; j < 16; ++j) {
            float4 a = zr[2 * j], b = zr[2 * j + 1];
            s += a.x * a.x; s += a.y * a.y; s += a.z * a.z; s += a.w * a.w;
            s += b.x * b.x; s += b.y * b.y; s += b.z * b.z; s += b.w * b.w;
            __nv_bfloat162 h0 = __floats2bfloat162_rn(a.x, a.y);
            __nv_bfloat162 h1 = __floats2bfloat162_rn(a.z, a.w);
            __nv_bfloat162 h2 = __floats2bfloat162_rn(b.x, b.y);
            __nv_bfloat162 h3 = __floats2bfloat162_rn(b.z, b.w);
            uint4 pk;
            pk.x = *(uint32_t*)&h0; pk.y = *(uint32_t*)&h1;
            pk.z = *(uint32_t*)&h2; pk.w = *(uint32_t*)&h3;
            *(uint4*)(arow + j * 16) = pk;
        }
        tmp[tid] = s;
    }
    __syncthreads();
    if (tid < 128) zns[tid] = tmp[2 * tid] + tmp[2 * tid + 1];
    __syncthreads();

    // per-thread rows: rs 0..3 -> mwarp*32 + (rs>>1)*16 + (rs&1)*8 + lane/4
    int rloc[4]; float zn[4];
    #pragma unroll
    for (int rs = 0; rs < 4; ++rs) {
        rloc[rs] = mwarp * 32 + (rs >> 1) * 16 + (rs & 1) * 8 + (lane >> 2);
        zn[rs] = zns[rloc[rs]];
    }

    float bv[4][2]; int bj[4][2];
    #pragma unroll
    for (int rs = 0; rs < 4; ++rs) { bv[rs][0] = bv[rs][1] = FLT_MAX; bj[rs][0] = bj[rs][1] = 0; }

    // ldmatrix address bases (within smem, bytes)
    const uint32_t aoff = sb + SM_A +
        (mwarp * 32 + (lane & 7) + ((lane >> 3) & 1) * 8) * RST + (lane >> 4) * 16;
    const uint32_t boff =
        (nwarp * 32 + (lane & 7) + ((lane >> 4) & 1) * 8) * RST + ((lane >> 3) & 1) * 16;

    prefetch_B(sb + SM_B0, 0, tid);

    for (int ct = 0; ct < 16; ++ct) {
        CP_WAIT0();
        __syncthreads();
        if (ct < 15) prefetch_B(sb + ((ct & 1) ? SM_B0 : SM_B1), ct + 1, tid);
        const uint32_t Bb = ((ct & 1) ? SM_B1 : SM_B0) + sb + boff;

        float c[2][4][4];
        #pragma unroll
        for (int t = 0; t < 2; ++t)
            #pragma unroll
            for (int g = 0; g < 4; ++g)
                #pragma unroll
                for (int q = 0; q < 4; ++q) c[t][g][q] = 0.f;

        #pragma unroll
        for (int kk = 0; kk < 16; ++kk) {
            uint32_t a00, a01, a02, a03, a10, a11, a12, a13;
            LDSM_X4(a00, a01, a02, a03, aoff + kk * 32);
            LDSM_X4(a10, a11, a12, a13, aoff + 16 * RST + kk * 32);
            uint32_t b00, b01, b10, b11, b20, b21, b30, b31;
            LDSM_X4(b00, b01, b10, b11, Bb + kk * 32);
            LDSM_X4(b20, b21, b30, b31, Bb + 16 * RST + kk * 32);
            MMA16816(c[0][0][0], c[0][0][1], c[0][0][2], c[0][0][3], a00, a01, a02, a03, b00, b01);
            MMA16816(c[0][1][0], c[0][1][1], c[0][1][2], c[0][1][3], a00, a01, a02, a03, b10, b11);
            MMA16816(c[0][2][0], c[0][2][1], c[0][2][2], c[0][2][3], a00, a01, a02, a03, b20, b21);
            MMA16816(c[0][3][0], c[0][3][1], c[0][3][2], c[0][3][3], a00, a01, a02, a03, b30, b31);
            MMA16816(c[1][0][0], c[1][0][1], c[1][0][2], c[1][0][3], a10, a11, a12, a13, b00, b01);
            MMA16816(c[1][1][0], c[1][1][1], c[1][1][2], c[1][1][3], a10, a11, a12, a13, b10, b11);
            MMA16816(c[1][2][0], c[1][2][1], c[1][2][2], c[1][2][3], a10, a11, a12, a13, b20, b21);
            MMA16816(c[1][3][0], c[1][3][1], c[1][3][2], c[1][3][3], a10, a11, a12, a13, b30, b31);
        }

        // scores + per-row top-2
        #pragma unroll
        for (int t = 0; t < 2; ++t)
            #pragma unroll
            for (int g = 0; g < 4; ++g) {
                const int n0 = ct * 64 + nwarp * 32 + g * 8 + (lane & 3) * 2;
                const float e0 = ens[n0], e1 = ens[n0 + 1];
                const int rsA = t * 2, rsB = t * 2 + 1;
                float s;
                s = fmaf(-2.0f, c[t][g][0], zn[rsA] + e0); INS2(bv[rsA], bj[rsA], s, n0);
                s = fmaf(-2.0f, c[t][g][1], zn[rsA] + e1); INS2(bv[rsA], bj[rsA], s, n0 + 1);
                s = fmaf(-2.0f, c[t][g][2], zn[rsB] + e0); INS2(bv[rsB], bj[rsB], s, n0);
                s = fmaf(-2.0f, c[t][g][3], zn[rsB] + e1); INS2(bv[rsB], bj[rsB], s, n0 + 1);
            }
        __syncthreads();   // done reading B buffer before it is overwritten
    }

    // ---- candidate merge + exact rescore ----
    unsigned long long* cand   = (unsigned long long*)(smem + SM_CAND);
    unsigned long long* rowres = (unsigned long long*)(smem + SM_ROWRES);
    int2* list = (int2*)(smem + SM_LIST);
    int*  cnt  = (int*)(smem + SM_CNT);

    if (tid == 0) *cnt = 0;
    __syncthreads();   // tmp (aliases cand) no longer needed
    #pragma unroll
    for (int rs = 0; rs < 4; ++rs) {
        int slot = (nwarp * 4 + (lane & 3)) * 2;
        cand[rloc[rs] * 16 + slot] =
            ((unsigned long long)__float_as_uint(bv[rs][0]) << 32) | (unsigned)bj[rs][0];
        cand[rloc[rs] * 16 + slot + 1] =
            ((unsigned long long)__float_as_uint(bv[rs][1]) << 32) | (unsigned)bj[rs][1];
    }
    __syncthreads();

    if (tid < 128) {
        unsigned long long best = cand[tid * 16];
        #pragma unroll
        for (int q = 1; q < 16; ++q) {
            unsigned long long e = cand[tid * 16 + q];
            if (e < best) best = e;
        }
        float bvv = __uint_as_float((uint32_t)(best >> 32));
        float thr = bvv + MARGIN;
        int nwithin = 0;
        #pragma unroll
        for (int q = 0; q < 16; ++q) {
            float v = __uint_as_float((uint32_t)(cand[tid * 16 + q] >> 32));
            if (v <= thr) nwithin++;
        }
        if (nwithin <= 1) {
            rowres[tid] = best;
        } else {
            rowres[tid] = 0xFFFFFFFFFFFFFFFFULL;
            #pragma unroll
            for (int q = 0; q < 16; ++q) {
                unsigned long long e = cand[tid * 16 + q];
                float v = __uint_as_float((uint32_t)(e >> 32));
                if (v <= thr) {
                    int p = atomicAdd(cnt, 1);
                    list[p] = make_int2(tid, (int)(e & 0xFFFFFFFFu));
                }
            }
        }
    }
    __syncthreads();

    // exact fp32 rescore: bit-identical to R1's validated recipe
    int nc = *cnt;
    for (int i = tid; i < nc; i += 256) {
        int row = list[i].x, code = list[i].y;
        const float4* zr = (const float4*)(zf + (size_t)(rowBase + row) * CDIM);
        const float4* er = (const float4*)(emb + (size_t)code * CDIM);
        float lo = 0.f, hi = 0.f;
        #pragma unroll 8
        for (int k = 0; k < 64; ++k) {
            float4 a = zr[k], e4 = er[k];
            lo = fmaf(a.x, e4.x, lo);
            hi = fmaf(a.y, e4.y, hi);
            lo = fmaf(a.z, e4.z, lo);
            hi = fmaf(a.w, e4.w, hi);
        }
        float dot = lo + hi;
        float s = (zns[row] + ens[code]) - 2.0f * dot;
        unsigned long long p =
            ((unsigned long long)__float_as_uint(s) << 32) | (unsigned)code;
        atomicMin(&rowres[row], p);
    }
    __syncthreads();

    if (tid < 128) {
        int wi = (int)(rowres[tid] & 0xFFFFFFFFu);
        int grow = rowBase + tid;
        g_idx[grow] = wi;
        out[OFF_IDX + grow] = (float)wi;
    }
}

// ---------------------------------------------------------------------------
// Epilogue + finalize (unchanged from R1; epilogue measured 42us, mem-balanced)
// ---------------------------------------------------------------------------
__global__ void __launch_bounds__(256)
vq_epilogue(const float* __restrict__ z, const float* __restrict__ emb,
            float* __restrict__ out) {
    __shared__ int   hist[NE];
    __shared__ float rbuf[256];
    int tid = threadIdx.x;
    #pragma unroll
    for (int i = tid; i < NE; i += 256) hist[i] = 0;
    __syncthreads();

    int rowBase = blockIdx.x * 32;
    float psum = 0.f;
    for (int rr = 0; rr < 32; ++rr) {
        int row = rowBase + rr;
        int idx = g_idx[row];
        float e  = emb[(size_t)idx * CDIM + tid];
        float zz = z[(size_t)row * CDIM + tid];
        float d  = e - zz;
        out[OFF_ZQ + (long long)row * CDIM + tid] = zz + d;
        psum += d * d;
    }
    if (tid < 32) {
        int row = rowBase + tid;
        int idx = g_idx[row];
        atomicAdd(&hist[idx], 1);
        out[OFF_ENC + (long long)row * NE + idx] = 1.0f;
    }
    rbuf[tid] = psum;
    __syncthreads();
    #pragma unroll
    for (int s = 128; s > 0; s >>= 1) {
        if (tid < s) rbuf[tid] += rbuf[tid + s];
        __syncthreads();
    }
    if (tid == 0) g_part[blockIdx.x] = rbuf[0];
    #pragma unroll
    for (int i = tid; i < NE; i += 256) {
        int h = hist[i];
        if (h) atomicAdd(&g_counts[i], h);
    }
}

__global__ void vq_finalize(float* __restrict__ out) {
    __shared__ double sd[256];
    int tid = threadIdx.x;
    double s = 0.0;
    for (int i = tid; i < 2048; i += 256) s += (double)g_part[i];
    sd[tid] = s;
    __syncthreads();
    #pragma unroll
    for (int st = 128; st > 0; st >>= 1) {
        if (tid < st) sd[tid] += sd[tid + st];
        __syncthreads();
    }
    if (tid == 0) {
        double mean = sd[0] / 16777216.0;
        out[OFF_LOSS] = (float)(mean + 0.25 * mean);
    }
    __syncthreads();
    double h = 0.0;
    for (int i = tid; i < NE; i += 256) {
        double m = (double)g_counts[i] / 65536.0;
        h += m * log(m + 1e-10);
    }
    sd[tid] = h;
    __syncthreads();
    #pragma unroll
    for (int st = 128; st > 0; st >>= 1) {
        if (tid < st) sd[tid] += sd[tid + st];
        __syncthreads();
    }
    if (tid == 0) out[OFF_PERP] = (float)exp(-sd[0]);
}

// ---------------------------------------------------------------------------
extern "C" void kernel_launch(void* const* d_in, const int* in_sizes, int n_in,
                              void* d_out, int out_size) {
    const float* z   = (const float*)d_in[0];
    const float* emb = (const float*)d_in[1];
    float* out = (float*)d_out;

    static int attr_done = 0;
    if (!attr_done) {
        cudaFuncSetAttribute(vq_main_mma,
                             cudaFuncAttributeMaxDynamicSharedMemorySize, SMEM_TC);
        attr_done = 1;
    }

    vq_init<<<1, NE>>>();
    vq_enorm<<<128, 256>>>(emb);
    vq_prep_e<<<128, 256>>>(emb);
    cudaMemsetAsync(out + OFF_ENC, 0, (size_t)NROWS * NE * sizeof(float));
    vq_main_mma<<<NROWS / 128, 256, SMEM_TC>>>(z, emb, out);
    vq_epilogue<<<NROWS / 32, 256>>>(z, emb, out);
    vq_finalize<<<1, 256>>>(out);
}

// round 4
// speedup vs baseline: 3.9670x; 1.1197x over previous
#include <cuda_runtime.h>
#include <cuda_bf16.h>
#include <cfloat>
#include <math.h>
#include <stdint.h>

// ---------------------------------------------------------------------------
// VectorQuantizer: z (32,2048,256) f32, emb (1024,256) f32
// Output layout (float32):
//   [0] loss | [1..16777217) z_q | [16777217] perplexity
//   [16777218..+67108864) one-hot | [83886082..+65536) indices
// R4: 512-thread CTAs (16 warps/SM), smem aliasing, stream-overlap memset,
// MLP-batched epilogue. Exact-rescore recipe unchanged (bit-validated R1/R3).
// ---------------------------------------------------------------------------

#define NROWS   65536
#define CDIM    256
#define NE      1024

#define OFF_LOSS 0LL
#define OFF_ZQ   1LL
#define OFF_PERP 16777217LL
#define OFF_ENC  16777218LL
#define OFF_IDX  83886082LL

#define MARGIN 1.5e-3f

// ----- device scratch -----
__device__ uint4 g_eb4[NE * CDIM / 8];      // emb as bf16 (row-major, 512KB)
__device__ float g_enorm[NE];
__device__ int   g_idx[NROWS];
__device__ float g_part[2048];
__device__ int   g_counts[NE];

// ======================= smem layout (bytes) ===============================
// Rows padded to 528 B (264 bf16): 8 consecutive rows spread across all 32
// banks per ldmatrix phase -> conflict-free.
#define RST 528
#define SM_A       0                      // 256*528 = 135168
#define SM_B0      135168                 // 64*528  = 33792
#define SM_B1      168960                 // 33792 (end 202752)
#define SM_EN      202752                 // 4096
#define SM_ZN      206848                 // 1024
#define SM_CNT     207872                 // 16
#define SM_TMP     207888                 // 2048 (znorm partials)
#define SMEM_TC    209936
// aliased onto dead A region after mainloop:
#define SM_CAND    0                      // 256*16*8 = 32768
#define SM_LIST    32768                  // 32768
#define SM_ROWRES  65536                  // 2048

// ======================= PTX helpers =======================================
__device__ __forceinline__ uint32_t smem_u32(const void* p) {
    uint32_t a;
    asm("{ .reg .u64 t; cvta.to.shared.u64 t, %1; cvt.u32.u64 %0, t; }"
        : "=r"(a) : "l"(p));
    return a;
}
#define LDSM_X4(r0, r1, r2, r3, addr) \
    asm volatile("ldmatrix.sync.aligned.m8n8.x4.shared.b16 {%0,%1,%2,%3}, [%4];" \
                 : "=r"(r0), "=r"(r1), "=r"(r2), "=r"(r3) : "r"(addr))
#define MMA16816(c0, c1, c2, c3, a0, a1, a2, a3, b0, b1) \
    asm volatile("mma.sync.aligned.m16n8k16.row.col.f32.bf16.bf16.f32 " \
                 "{%0,%1,%2,%3}, {%4,%5,%6,%7}, {%8,%9}, {%0,%1,%2,%3};" \
                 : "+f"(c0), "+f"(c1), "+f"(c2), "+f"(c3) \
                 : "r"(a0), "r"(a1), "r"(a2), "r"(a3), "r"(b0), "r"(b1))
#define CP16(dst, src) \
    asm volatile("cp.async.cg.shared.global [%0], [%1], 16;" :: "r"(dst), "l"(src))
#define CP_COMMIT() asm volatile("cp.async.commit_group;" ::: "memory")
#define CP_WAIT0()  asm volatile("cp.async.wait_group 0;" ::: "memory")

#define INS2(vv, jj, s, j) do {                                   \
    if ((s) < vv[1]) {                                            \
        if ((s) < vv[0]) { vv[1]=vv[0]; jj[1]=jj[0]; vv[0]=(s); jj[0]=(j); } \
        else             { vv[1]=(s); jj[1]=(j); }                \
    } } while (0)

// ---------------------------------------------------------------------------
__global__ void vq_init() { g_counts[threadIdx.x] = 0; }

// ||e_j||^2 — verbatim R1 rounding (validated: zero flips).
__global__ void vq_enorm(const float* __restrict__ emb) {
    int gw   = (blockIdx.x * blockDim.x + threadIdx.x) >> 5;
    int lane = threadIdx.x & 31;
    if (gw >= NE) return;
    const float* e = emb + (size_t)gw * CDIM;
    float s = 0.f;
    #pragma unroll
    for (int i = lane; i < CDIM; i += 32) { float x = e[i]; s += x * x; }
    #pragma unroll
    for (int o = 16; o > 0; o >>= 1) s += __shfl_down_sync(0xffffffffu, s, o);
    if (lane == 0) g_enorm[gw] = s;
}

// emb f32 -> bf16 (row-major)
__global__ void __launch_bounds__(256)
vq_prep_e(const float* __restrict__ emb) {
    int idx = blockIdx.x * 256 + threadIdx.x;        // 0..32767, 8 floats each
    const float4* s4 = (const float4*)emb + idx * 2;
    float4 a = s4[0], b = s4[1];
    __nv_bfloat162 h0 = __floats2bfloat162_rn(a.x, a.y);
    __nv_bfloat162 h1 = __floats2bfloat162_rn(a.z, a.w);
    __nv_bfloat162 h2 = __floats2bfloat162_rn(b.x, b.y);
    __nv_bfloat162 h3 = __floats2bfloat162_rn(b.z, b.w);
    uint4 pk;
    pk.x = *(uint32_t*)&h0; pk.y = *(uint32_t*)&h1;
    pk.z = *(uint32_t*)&h2; pk.w = *(uint32_t*)&h3;
    g_eb4[idx] = pk;
}

// Prefetch one 64-code bf16 tile into smem (padded rows) via cp.async.
__device__ __forceinline__ void prefetch_B(uint32_t sdst, int ct, int tid) {
    const char* gsrc = (const char*)g_eb4 + (size_t)ct * 64 * 512;
    #pragma unroll
    for (int j = 0; j < 4; ++j) {
        int idx = tid + j * 512;              // 0..2047
        int row = idx >> 5, g = idx & 31;
        CP16(sdst + row * RST + g * 16, gsrc + row * 512 + g * 16);
    }
    CP_COMMIT();
}

// ---------------------------------------------------------------------------
// Main kernel: 256 CTAs x 512 threads. CTA = 256 rows x 1024 codes.
// Warps: 8(M) x 2(N); warp tile 32 rows x 32 codes per 64-code smem tile.
// ---------------------------------------------------------------------------
__global__ void __launch_bounds__(512, 1)
vq_main_mma(const float* __restrict__ zf, const float* __restrict__ emb,
            float* __restrict__ out) {
    extern __shared__ char smem[];
    const uint32_t sb = smem_u32(smem);
    const int tid = threadIdx.x;
    const int lane = tid & 31, wid = tid >> 5;
    const int mwarp = wid & 7, nwarp = wid >> 3;
    const int rowBase = blockIdx.x * 256;

    // kick off first B tile immediately (overlaps A conversion)
    prefetch_B(sb + SM_B0, 0, tid);

    float* ens = (float*)(smem + SM_EN);
    float* zns = (float*)(smem + SM_ZN);
    float* tmp = (float*)(smem + SM_TMP);

    for (int i = tid; i < NE; i += 512) ens[i] = g_enorm[i];

    // ---- A tile: load z f32, convert to bf16 (padded smem), norm partials
    {
        int row = tid >> 1, half = tid & 1;
        const float4* zr = (const float4*)zf + ((size_t)(rowBase + row) * 64 + half * 32);
        char* arow = smem + SM_A + row * RST + half * 256;
        float s = 0.f;
        #pragma unroll 4
        for (int j = 0; j < 16; ++j) {
            float4 a = zr[2 * j], b = zr[2 * j + 1];
            s += a.x * a.x; s += a.y * a.y; s += a.z * a.z; s += a.w * a.w;
            s += b.x * b.x; s += b.y * b.y; s += b.z * b.z; s += b.w * b.w;
            __nv_bfloat162 h0 = __floats2bfloat162_rn(a.x, a.y);
            __nv_bfloat162 h1 = __floats2bfloat162_rn(a.z, a.w);
            __nv_bfloat162 h2 = __floats2bfloat162_rn(b.x, b.y);
            __nv_bfloat162 h3 = __floats2bfloat162_rn(b.z, b.w);
            uint4 pk;
            pk.x = *(uint32_t*)&h0; pk.y = *(uint32_t*)&h1;
            pk.z = *(uint32_t*)&h2; pk.w = *(uint32_t*)&h3;
            *(uint4*)(arow + j * 16) = pk;
        }
        tmp[tid] = s;
    }
    __syncthreads();
    if (tid < 256) zns[tid] = tmp[2 * tid] + tmp[2 * tid + 1];
    __syncthreads();

    // per-thread rows: rs 0..3 -> mwarp*32 + (rs>>1)*16 + (rs&1)*8 + lane/4
    int rloc[4]; float zn[4];
    #pragma unroll
    for (int rs = 0; rs < 4; ++rs) {
        rloc[rs] = mwarp * 32 + (rs >> 1) * 16 + (rs & 1) * 8 + (lane >> 2);
        zn[rs] = zns[rloc[rs]];
    }

    float bv[4][2]; int bj[4][2];
    #pragma unroll
    for (int rs = 0; rs < 4; ++rs) { bv[rs][0] = bv[rs][1] = FLT_MAX; bj[rs][0] = bj[rs][1] = 0; }

    // ldmatrix address bases (bytes)
    const uint32_t aoff = sb + SM_A +
        (mwarp * 32 + (lane & 7) + ((lane >> 3) & 1) * 8) * RST + (lane >> 4) * 16;
    const uint32_t boff =
        (nwarp * 32 + (lane & 7) + ((lane >> 4) & 1) * 8) * RST + ((lane >> 3) & 1) * 16;

    for (int ct = 0; ct < 16; ++ct) {
        CP_WAIT0();
        __syncthreads();
        if (ct < 15) prefetch_B(sb + ((ct & 1) ? SM_B0 : SM_B1), ct + 1, tid);
        const uint32_t Bb = ((ct & 1) ? SM_B1 : SM_B0) + sb + boff;

        float c[2][4][4];
        #pragma unroll
        for (int t = 0; t < 2; ++t)
            #pragma unroll
            for (int g = 0; g < 4; ++g)
                #pragma unroll
                for (int q = 0; q < 4; ++q) c[t][g][q] = 0.f;

        #pragma unroll
        for (int kk = 0; kk < 16; ++kk) {
            uint32_t a00, a01, a02, a03, a10, a11, a12, a13;
            LDSM_X4(a00, a01, a02, a03, aoff + kk * 32);
            LDSM_X4(a10, a11, a12, a13, aoff + 16 * RST + kk * 32);
            uint32_t b00, b01, b10, b11, b20, b21, b30, b31;
            LDSM_X4(b00, b01, b10, b11, Bb + kk * 32);
            LDSM_X4(b20, b21, b30, b31, Bb + 16 * RST + kk * 32);
            MMA16816(c[0][0][0], c[0][0][1], c[0][0][2], c[0][0][3], a00, a01, a02, a03, b00, b01);
            MMA16816(c[0][1][0], c[0][1][1], c[0][1][2], c[0][1][3], a00, a01, a02, a03, b10, b11);
            MMA16816(c[0][2][0], c[0][2][1], c[0][2][2], c[0][2][3], a00, a01, a02, a03, b20, b21);
            MMA16816(c[0][3][0], c[0][3][1], c[0][3][2], c[0][3][3], a00, a01, a02, a03, b30, b31);
            MMA16816(c[1][0][0], c[1][0][1], c[1][0][2], c[1][0][3], a10, a11, a12, a13, b00, b01);
            MMA16816(c[1][1][0], c[1][1][1], c[1][1][2], c[1][1][3], a10, a11, a12, a13, b10, b11);
            MMA16816(c[1][2][0], c[1][2][1], c[1][2][2], c[1][2][3], a10, a11, a12, a13, b20, b21);
            MMA16816(c[1][3][0], c[1][3][1], c[1][3][2], c[1][3][3], a10, a11, a12, a13, b30, b31);
        }

        // scores + per-row top-2
        #pragma unroll
        for (int t = 0; t < 2; ++t)
            #pragma unroll
            for (int g = 0; g < 4; ++g) {
                const int n0 = ct * 64 + nwarp * 32 + g * 8 + (lane & 3) * 2;
                const float e0 = ens[n0], e1 = ens[n0 + 1];
                const int rsA = t * 2, rsB = t * 2 + 1;
                float s;
                s = fmaf(-2.0f, c[t][g][0], zn[rsA] + e0); INS2(bv[rsA], bj[rsA], s, n0);
                s = fmaf(-2.0f, c[t][g][1], zn[rsA] + e1); INS2(bv[rsA], bj[rsA], s, n0 + 1);
                s = fmaf(-2.0f, c[t][g][2], zn[rsB] + e0); INS2(bv[rsB], bj[rsB], s, n0);
                s = fmaf(-2.0f, c[t][g][3], zn[rsB] + e1); INS2(bv[rsB], bj[rsB], s, n0 + 1);
            }
        __syncthreads();   // done reading B buffer before it is overwritten
    }

    // ---- candidate merge + exact rescore (cand/list/rowres alias dead A) --
    unsigned long long* cand   = (unsigned long long*)(smem + SM_CAND);
    unsigned long long* rowres = (unsigned long long*)(smem + SM_ROWRES);
    int2* list = (int2*)(smem + SM_LIST);
    int*  cnt  = (int*)(smem + SM_CNT);

    if (tid == 0) *cnt = 0;
    #pragma unroll
    for (int rs = 0; rs < 4; ++rs) {
        int slot = (nwarp * 4 + (lane & 3)) * 2;
        cand[rloc[rs] * 16 + slot] =
            ((unsigned long long)__float_as_uint(bv[rs][0]) << 32) | (unsigned)bj[rs][0];
        cand[rloc[rs] * 16 + slot + 1] =
            ((unsigned long long)__float_as_uint(bv[rs][1]) << 32) | (unsigned)bj[rs][1];
    }
    __syncthreads();

    if (tid < 256) {
        unsigned long long best = cand[tid * 16];
        #pragma unroll
        for (int q = 1; q < 16; ++q) {
            unsigned long long e = cand[tid * 16 + q];
            if (e < best) best = e;
        }
        float bvv = __uint_as_float((uint32_t)(best >> 32));
        float thr = bvv + MARGIN;
        int nwithin = 0;
        #pragma unroll
        for (int q = 0; q < 16; ++q) {
            float v = __uint_as_float((uint32_t)(cand[tid * 16 + q] >> 32));
            if (v <= thr) nwithin++;
        }
        if (nwithin <= 1) {
            rowres[tid] = best;
        } else {
            rowres[tid] = 0xFFFFFFFFFFFFFFFFULL;
            #pragma unroll
            for (int q = 0; q < 16; ++q) {
                unsigned long long e = cand[tid * 16 + q];
                float v = __uint_as_float((uint32_t)(e >> 32));
                if (v <= thr) {
                    int p = atomicAdd(cnt, 1);
                    list[p] = make_int2(tid, (int)(e & 0xFFFFFFFFu));
                }
            }
        }
    }
    __syncthreads();

    // exact fp32 rescore: bit-identical to R1's validated recipe
    int nc = *cnt;
    for (int i = tid; i < nc; i += 512) {
        int row = list[i].x, code = list[i].y;
        const float4* zr = (const float4*)(zf + (size_t)(rowBase + row) * CDIM);
        const float4* er = (const float4*)(emb + (size_t)code * CDIM);
        float lo = 0.f, hi = 0.f;
        #pragma unroll 4
        for (int k = 0; k < 64; ++k) {
            float4 a = zr[k], e4 = er[k];
            lo = fmaf(a.x, e4.x, lo);
            hi = fmaf(a.y, e4.y, hi);
            lo = fmaf(a.z, e4.z, lo);
            hi = fmaf(a.w, e4.w, hi);
        }
        float dot = lo + hi;
        float s = (zns[row] + ens[code]) - 2.0f * dot;
        unsigned long long p =
            ((unsigned long long)__float_as_uint(s) << 32) | (unsigned)code;
        atomicMin(&rowres[row], p);
    }
    __syncthreads();

    if (tid < 256) {
        int wi = (int)(rowres[tid] & 0xFFFFFFFFu);
        int grow = rowBase + tid;
        g_idx[grow] = wi;
        out[OFF_IDX + grow] = (float)wi;
    }
}

// ---------------------------------------------------------------------------
// Epilogue: 4-row LDG batching (MLP 8) + one-hot scatter + loss + histogram.
// ---------------------------------------------------------------------------
__global__ void __launch_bounds__(256)
vq_epilogue(const float* __restrict__ z, const float* __restrict__ emb,
            float* __restrict__ out) {
    __shared__ int   hist[NE];
    __shared__ float rbuf[256];
    int tid = threadIdx.x;
    #pragma unroll
    for (int i = tid; i < NE; i += 256) hist[i] = 0;
    __syncthreads();

    int rowBase = blockIdx.x * 32;
    float psum = 0.f;
    for (int rr = 0; rr < 32; rr += 4) {
        float ev[4], zv[4];
        #pragma unroll
        for (int q = 0; q < 4; ++q) {
            int row = rowBase + rr + q;
            int idx = g_idx[row];
            ev[q] = emb[(size_t)idx * CDIM + tid];
            zv[q] = z[(size_t)row * CDIM + tid];
        }
        #pragma unroll
        for (int q = 0; q < 4; ++q) {
            int row = rowBase + rr + q;
            float d = ev[q] - zv[q];
            out[OFF_ZQ + (long long)row * CDIM + tid] = zv[q] + d;
            psum += d * d;
        }
    }
    if (tid < 32) {
        int row = rowBase + tid;
        int idx = g_idx[row];
        atomicAdd(&hist[idx], 1);
        out[OFF_ENC + (long long)row * NE + idx] = 1.0f;
    }
    rbuf[tid] = psum;
    __syncthreads();
    #pragma unroll
    for (int s = 128; s > 0; s >>= 1) {
        if (tid < s) rbuf[tid] += rbuf[tid + s];
        __syncthreads();
    }
    if (tid == 0) g_part[blockIdx.x] = rbuf[0];
    #pragma unroll
    for (int i = tid; i < NE; i += 256) {
        int h = hist[i];
        if (h) atomicAdd(&g_counts[i], h);
    }
}

__global__ void vq_finalize(float* __restrict__ out) {
    __shared__ double sd[256];
    int tid = threadIdx.x;
    double s = 0.0;
    for (int i = tid; i < 2048; i += 256) s += (double)g_part[i];
    sd[tid] = s;
    __syncthreads();
    #pragma unroll
    for (int st = 128; st > 0; st >>= 1) {
        if (tid < st) sd[tid] += sd[tid + st];
        __syncthreads();
    }
    if (tid == 0) {
        double mean = sd[0] / 16777216.0;
        out[OFF_LOSS] = (float)(mean + 0.25 * mean);
    }
    __syncthreads();
    double h = 0.0;
    for (int i = tid; i < NE; i += 256) {
        double m = (double)g_counts[i] / 65536.0;
        h += m * log(m + 1e-10);
    }
    sd[tid] = h;
    __syncthreads();
    #pragma unroll
    for (int st = 128; st > 0; st >>= 1) {
        if (tid < st) sd[tid] += sd[tid + st];
        __syncthreads();
    }
    if (tid == 0) out[OFF_PERP] = (float)exp(-sd[0]);
}

// ---------------------------------------------------------------------------
extern "C" void kernel_launch(void* const* d_in, const int* in_sizes, int n_in,
                              void* d_out, int out_size) {
    const float* z   = (const float*)d_in[0];
    const float* emb = (const float*)d_in[1];
    float* out = (float*)d_out;

    static int init_done = 0;
    static cudaStream_t s2;
    static cudaEvent_t evFork, evJoin;
    if (!init_done) {
        cudaFuncSetAttribute(vq_main_mma,
                             cudaFuncAttributeMaxDynamicSharedMemorySize, SMEM_TC);
        cudaStreamCreateWithFlags(&s2, cudaStreamNonBlocking);
        cudaEventCreateWithFlags(&evFork, cudaEventDisableTiming);
        cudaEventCreateWithFlags(&evJoin, cudaEventDisableTiming);
        init_done = 1;
    }

    // fork: big one-hot memset runs concurrently with the compute-bound main
    cudaEventRecord(evFork, 0);
    cudaStreamWaitEvent(s2, evFork, 0);
    cudaMemsetAsync(out + OFF_ENC, 0, (size_t)NROWS * NE * sizeof(float), s2);
    cudaEventRecord(evJoin, s2);

    vq_init<<<1, NE>>>();
    vq_enorm<<<128, 256>>>(emb);
    vq_prep_e<<<128, 256>>>(emb);
    vq_main_mma<<<NROWS / 256, 512, SMEM_TC>>>(z, emb, out);

    // join: epilogue scatters into the memset region
    cudaStreamWaitEvent(0, evJoin, 0);
    vq_epilogue<<<NROWS / 32, 256>>>(z, emb, out);
    vq_finalize<<<1, 256>>>(out);
}

// round 5
// speedup vs baseline: 4.1061x; 1.0351x over previous
#include <cuda_runtime.h>
#include <cuda_bf16.h>
#include <cfloat>
#include <math.h>
#include <stdint.h>

// ---------------------------------------------------------------------------
// VectorQuantizer: z (32,2048,256) f32, emb (1024,256) f32
// Output layout (float32):
//   [0] loss | [1..16777217) z_q | [16777217] perplexity
//   [16777218..+67108864) one-hot | [83886082..+65536) indices
// R5: fully fused — main kernel computes argmin AND writes one-hot, z_q,
// loss partials, histogram (no memset, no separate epilogue). Single barrier
// per mainloop iteration. Exact-rescore recipe unchanged (bit-validated).
// ---------------------------------------------------------------------------

#define NROWS   65536
#define CDIM    256
#define NE      1024

#define OFF_LOSS 0LL
#define OFF_ZQ   1LL
#define OFF_PERP 16777217LL
#define OFF_ENC  16777218LL
#define OFF_IDX  83886082LL

#define MARGIN 1.5e-3f

// ----- device scratch -----
__device__ uint4 g_eb4[NE * CDIM / 8];      // emb as bf16 (row-major, 512KB)
__device__ float g_enorm[NE];
__device__ float g_part[256];
__device__ int   g_counts[NE];

// ======================= smem layout (bytes) ===============================
#define RST 528
#define SM_A       0                      // 256*528 = 135168
#define SM_B0      135168                 // 33792
#define SM_B1      168960                 // 33792 (end 202752)
#define SM_EN      202752                 // 4096
#define SM_ZN      206848                 // 1024
#define SM_CNT     207872                 // 16
#define SM_TMP     207888                 // 2048 (znorm partials, later idxs)
#define SMEM_TC    209936
// aliases in dead A region after mainloop:
#define SM_CAND    0                      // 32768
#define SM_LIST    32768                  // 32768
#define SM_ROWRES  65536                  // 2048
#define SM_HIST    67584                  // 4096
#define SM_RBUF    71680                  // 2048
#define SM_SBUF    73728                  // 16 warps * 1KB = 16384

// ======================= PTX helpers =======================================
__device__ __forceinline__ uint32_t smem_u32(const void* p) {
    uint32_t a;
    asm("{ .reg .u64 t; cvta.to.shared.u64 t, %1; cvt.u32.u64 %0, t; }"
        : "=r"(a) : "l"(p));
    return a;
}
#define LDSM_X4(r0, r1, r2, r3, addr) \
    asm volatile("ldmatrix.sync.aligned.m8n8.x4.shared.b16 {%0,%1,%2,%3}, [%4];" \
                 : "=r"(r0), "=r"(r1), "=r"(r2), "=r"(r3) : "r"(addr))
#define MMA16816(c0, c1, c2, c3, a0, a1, a2, a3, b0, b1) \
    asm volatile("mma.sync.aligned.m16n8k16.row.col.f32.bf16.bf16.f32 " \
                 "{%0,%1,%2,%3}, {%4,%5,%6,%7}, {%8,%9}, {%0,%1,%2,%3};" \
                 : "+f"(c0), "+f"(c1), "+f"(c2), "+f"(c3) \
                 : "r"(a0), "r"(a1), "r"(a2), "r"(a3), "r"(b0), "r"(b1))
#define CP16(dst, src) \
    asm volatile("cp.async.cg.shared.global [%0], [%1], 16;" :: "r"(dst), "l"(src))
#define CP_COMMIT() asm volatile("cp.async.commit_group;" ::: "memory")
#define CP_WAIT0()  asm volatile("cp.async.wait_group 0;" ::: "memory")

#define INS2(vv, jj, s, j) do {                                   \
    if ((s) < vv[1]) {                                            \
        if ((s) < vv[0]) { vv[1]=vv[0]; jj[1]=jj[0]; vv[0]=(s); jj[0]=(j); } \
        else             { vv[1]=(s); jj[1]=(j); }                \
    } } while (0)

// ---------------------------------------------------------------------------
__global__ void vq_init() { g_counts[threadIdx.x] = 0; }

// Fused: ||e_j||^2 (verbatim R1 rounding) + f32->bf16 pack. One warp/code.
__global__ void __launch_bounds__(256)
vq_prep(const float* __restrict__ emb) {
    int gw   = (blockIdx.x * blockDim.x + threadIdx.x) >> 5;
    int lane = threadIdx.x & 31;
    const float* e = emb + (size_t)gw * CDIM;
    float s = 0.f;
    #pragma unroll
    for (int i = lane; i < CDIM; i += 32) { float x = e[i]; s += x * x; }
    #pragma unroll
    for (int o = 16; o > 0; o >>= 1) s += __shfl_down_sync(0xffffffffu, s, o);
    if (lane == 0) g_enorm[gw] = s;

    const float4* s4 = (const float4*)e;
    float4 a = s4[lane * 2], b = s4[lane * 2 + 1];
    __nv_bfloat162 h0 = __floats2bfloat162_rn(a.x, a.y);
    __nv_bfloat162 h1 = __floats2bfloat162_rn(a.z, a.w);
    __nv_bfloat162 h2 = __floats2bfloat162_rn(b.x, b.y);
    __nv_bfloat162 h3 = __floats2bfloat162_rn(b.z, b.w);
    uint4 pk;
    pk.x = *(uint32_t*)&h0; pk.y = *(uint32_t*)&h1;
    pk.z = *(uint32_t*)&h2; pk.w = *(uint32_t*)&h3;
    g_eb4[(size_t)gw * 32 + lane] = pk;
}

// Prefetch one 64-code bf16 tile into smem (padded rows) via cp.async.
__device__ __forceinline__ void prefetch_B(uint32_t sdst, int ct, int tid) {
    const char* gsrc = (const char*)g_eb4 + (size_t)ct * 64 * 512;
    #pragma unroll
    for (int j = 0; j < 4; ++j) {
        int idx = tid + j * 512;              // 0..2047
        int row = idx >> 5, g = idx & 31;
        CP16(sdst + row * RST + g * 16, gsrc + row * 512 + g * 16);
    }
    CP_COMMIT();
}

// ---------------------------------------------------------------------------
// Fused main: 256 CTAs x 512 threads. CTA = 256 rows x 1024 codes.
// ---------------------------------------------------------------------------
__global__ void __launch_bounds__(512, 1)
vq_main_fused(const float* __restrict__ zf, const float* __restrict__ emb,
              float* __restrict__ out) {
    extern __shared__ char smem[];
    const uint32_t sb = smem_u32(smem);
    const int tid = threadIdx.x;
    const int lane = tid & 31, wid = tid >> 5;
    const int mwarp = wid & 7, nwarp = wid >> 3;
    const int rowBase = blockIdx.x * 256;

    prefetch_B(sb + SM_B0, 0, tid);

    float* ens = (float*)(smem + SM_EN);
    float* zns = (float*)(smem + SM_ZN);
    float* tmp = (float*)(smem + SM_TMP);

    for (int i = tid; i < NE; i += 512) ens[i] = g_enorm[i];

    // ---- A tile: load z f32, convert to bf16 (padded smem), norm partials
    {
        int row = tid >> 1, half = tid & 1;
        const float4* zr = (const float4*)zf + ((size_t)(rowBase + row) * 64 + half * 32);
        char* arow = smem + SM_A + row * RST + half * 256;
        float s = 0.f;
        #pragma unroll 4
        for (int j = 0; j < 16; ++j) {
            float4 a = zr[2 * j], b = zr[2 * j + 1];
            s += a.x * a.x; s += a.y * a.y; s += a.z * a.z; s += a.w * a.w;
            s += b.x * b.x; s += b.y * b.y; s += b.z * b.z; s += b.w * b.w;
            __nv_bfloat162 h0 = __floats2bfloat162_rn(a.x, a.y);
            __nv_bfloat162 h1 = __floats2bfloat162_rn(a.z, a.w);
            __nv_bfloat162 h2 = __floats2bfloat162_rn(b.x, b.y);
            __nv_bfloat162 h3 = __floats2bfloat162_rn(b.z, b.w);
            uint4 pk;
            pk.x = *(uint32_t*)&h0; pk.y = *(uint32_t*)&h1;
            pk.z = *(uint32_t*)&h2; pk.w = *(uint32_t*)&h3;
            *(uint4*)(arow + j * 16) = pk;
        }
        tmp[tid] = s;
    }
    __syncthreads();
    if (tid < 256) zns[tid] = tmp[2 * tid] + tmp[2 * tid + 1];
    __syncthreads();

    int rloc[4]; float zn[4];
    #pragma unroll
    for (int rs = 0; rs < 4; ++rs) {
        rloc[rs] = mwarp * 32 + (rs >> 1) * 16 + (rs & 1) * 8 + (lane >> 2);
        zn[rs] = zns[rloc[rs]];
    }

    float bv[4][2]; int bj[4][2];
    #pragma unroll
    for (int rs = 0; rs < 4; ++rs) { bv[rs][0] = bv[rs][1] = FLT_MAX; bj[rs][0] = bj[rs][1] = 0; }

    const uint32_t aoff = sb + SM_A +
        (mwarp * 32 + (lane & 7) + ((lane >> 3) & 1) * 8) * RST + (lane >> 4) * 16;
    const uint32_t boff =
        (nwarp * 32 + (lane & 7) + ((lane >> 4) & 1) * 8) * RST + ((lane >> 3) & 1) * 16;

    for (int ct = 0; ct < 16; ++ct) {
        CP_WAIT0();
        __syncthreads();   // data ready for all; all warps are past ct-1 reads
        if (ct < 15) prefetch_B(sb + ((ct & 1) ? SM_B0 : SM_B1), ct + 1, tid);
        const uint32_t Bb = ((ct & 1) ? SM_B1 : SM_B0) + sb + boff;

        float c[2][4][4];
        #pragma unroll
        for (int t = 0; t < 2; ++t)
            #pragma unroll
            for (int g = 0; g < 4; ++g)
                #pragma unroll
                for (int q = 0; q < 4; ++q) c[t][g][q] = 0.f;

        #pragma unroll
        for (int kk = 0; kk < 16; ++kk) {
            uint32_t a00, a01, a02, a03, a10, a11, a12, a13;
            LDSM_X4(a00, a01, a02, a03, aoff + kk * 32);
            LDSM_X4(a10, a11, a12, a13, aoff + 16 * RST + kk * 32);
            uint32_t b00, b01, b10, b11, b20, b21, b30, b31;
            LDSM_X4(b00, b01, b10, b11, Bb + kk * 32);
            LDSM_X4(b20, b21, b30, b31, Bb + 16 * RST + kk * 32);
            MMA16816(c[0][0][0], c[0][0][1], c[0][0][2], c[0][0][3], a00, a01, a02, a03, b00, b01);
            MMA16816(c[0][1][0], c[0][1][1], c[0][1][2], c[0][1][3], a00, a01, a02, a03, b10, b11);
            MMA16816(c[0][2][0], c[0][2][1], c[0][2][2], c[0][2][3], a00, a01, a02, a03, b20, b21);
            MMA16816(c[0][3][0], c[0][3][1], c[0][3][2], c[0][3][3], a00, a01, a02, a03, b30, b31);
            MMA16816(c[1][0][0], c[1][0][1], c[1][0][2], c[1][0][3], a10, a11, a12, a13, b00, b01);
            MMA16816(c[1][1][0], c[1][1][1], c[1][1][2], c[1][1][3], a10, a11, a12, a13, b10, b11);
            MMA16816(c[1][2][0], c[1][2][1], c[1][2][2], c[1][2][3], a10, a11, a12, a13, b20, b21);
            MMA16816(c[1][3][0], c[1][3][1], c[1][3][2], c[1][3][3], a10, a11, a12, a13, b30, b31);
        }

        #pragma unroll
        for (int t = 0; t < 2; ++t)
            #pragma unroll
            for (int g = 0; g < 4; ++g) {
                const int n0 = ct * 64 + nwarp * 32 + g * 8 + (lane & 3) * 2;
                const float e0 = ens[n0], e1 = ens[n0 + 1];
                const int rsA = t * 2, rsB = t * 2 + 1;
                float s;
                s = fmaf(-2.0f, c[t][g][0], zn[rsA] + e0); INS2(bv[rsA], bj[rsA], s, n0);
                s = fmaf(-2.0f, c[t][g][1], zn[rsA] + e1); INS2(bv[rsA], bj[rsA], s, n0 + 1);
                s = fmaf(-2.0f, c[t][g][2], zn[rsB] + e0); INS2(bv[rsB], bj[rsB], s, n0);
                s = fmaf(-2.0f, c[t][g][3], zn[rsB] + e1); INS2(bv[rsB], bj[rsB], s, n0 + 1);
            }
        // no trailing barrier: next iteration's top barrier protects the buffer
    }
    __syncthreads();   // all ldsm/A reads done before aliasing A region

    // ---- candidate merge + exact rescore (aliased onto dead A region) -----
    unsigned long long* cand   = (unsigned long long*)(smem + SM_CAND);
    unsigned long long* rowres = (unsigned long long*)(smem + SM_ROWRES);
    int2* list = (int2*)(smem + SM_LIST);
    int*  cnt  = (int*)(smem + SM_CNT);

    if (tid == 0) *cnt = 0;
    #pragma unroll
    for (int rs = 0; rs < 4; ++rs) {
        int slot = (nwarp * 4 + (lane & 3)) * 2;
        cand[rloc[rs] * 16 + slot] =
            ((unsigned long long)__float_as_uint(bv[rs][0]) << 32) | (unsigned)bj[rs][0];
        cand[rloc[rs] * 16 + slot + 1] =
            ((unsigned long long)__float_as_uint(bv[rs][1]) << 32) | (unsigned)bj[rs][1];
    }
    __syncthreads();

    if (tid < 256) {
        unsigned long long best = cand[tid * 16];
        #pragma unroll
        for (int q = 1; q < 16; ++q) {
            unsigned long long e = cand[tid * 16 + q];
            if (e < best) best = e;
        }
        float bvv = __uint_as_float((uint32_t)(best >> 32));
        float thr = bvv + MARGIN;
        int nwithin = 0;
        #pragma unroll
        for (int q = 0; q < 16; ++q) {
            float v = __uint_as_float((uint32_t)(cand[tid * 16 + q] >> 32));
            if (v <= thr) nwithin++;
        }
        if (nwithin <= 1) {
            rowres[tid] = best;
        } else {
            rowres[tid] = 0xFFFFFFFFFFFFFFFFULL;
            #pragma unroll
            for (int q = 0; q < 16; ++q) {
                unsigned long long e = cand[tid * 16 + q];
                float v = __uint_as_float((uint32_t)(e >> 32));
                if (v <= thr) {
                    int p = atomicAdd(cnt, 1);
                    list[p] = make_int2(tid, (int)(e & 0xFFFFFFFFu));
                }
            }
        }
    }
    __syncthreads();

    int nc = *cnt;
    for (int i = tid; i < nc; i += 512) {
        int row = list[i].x, code = list[i].y;
        const float4* zr = (const float4*)(zf + (size_t)(rowBase + row) * CDIM);
        const float4* er = (const float4*)(emb + (size_t)code * CDIM);
        float lo = 0.f, hi = 0.f;
        #pragma unroll 4
        for (int k = 0; k < 64; ++k) {
            float4 a = zr[k], e4 = er[k];
            lo = fmaf(a.x, e4.x, lo);
            hi = fmaf(a.y, e4.y, hi);
            lo = fmaf(a.z, e4.z, lo);
            hi = fmaf(a.w, e4.w, hi);
        }
        float dot = lo + hi;
        float s = (zns[row] + ens[code]) - 2.0f * dot;
        unsigned long long p =
            ((unsigned long long)__float_as_uint(s) << 32) | (unsigned)code;
        atomicMin(&rowres[row], p);
    }
    __syncthreads();

    // ---- finalize indices + fused epilogue ----
    int* idxs = (int*)(smem + SM_TMP);
    int* hist = (int*)(smem + SM_HIST);
    for (int i = tid; i < NE; i += 512) hist[i] = 0;
    __syncthreads();
    if (tid < 256) {
        int wi = (int)(rowres[tid] & 0xFFFFFFFFu);
        idxs[tid] = wi;
        out[OFF_IDX + rowBase + tid] = (float)wi;
        atomicAdd(&hist[wi], 1);
    }
    __syncthreads();

    // z_q + loss (warp-per-row, staged in smem for aligned stores)
    float* sbuf = (float*)(smem + SM_SBUF) + wid * 256;
    float psum = 0.f;
    for (int rr = 0; rr < 16; ++rr) {
        const int row = wid * 16 + rr;
        const int idx = idxs[row];
        const float4* zr4 = (const float4*)zf + (size_t)(rowBase + row) * 64;
        const float4* er4 = (const float4*)emb + (size_t)idx * 64;
        #pragma unroll
        for (int it = 0; it < 2; ++it) {
            int k4 = it * 32 + lane;
            float4 a = zr4[k4], e = er4[k4];
            float dx = e.x - a.x, dy = e.y - a.y, dz = e.z - a.z, dw = e.w - a.w;
            psum += dx * dx + dy * dy + dz * dz + dw * dw;
            float4 q = {a.x + dx, a.y + dy, a.z + dz, a.w + dw};
            *(float4*)&sbuf[k4 * 4] = q;
        }
        __syncwarp();
        float* og = out + OFF_ZQ + (size_t)(rowBase + row) * 256;
        if (lane == 0) og[0] = sbuf[0];
        else if (lane == 1) { float2 t = {sbuf[1], sbuf[2]}; *(float2*)(og + 1) = t; }
        else if (lane == 2) og[255] = sbuf[255];
        #pragma unroll
        for (int c = lane; c < 63; c += 32) {
            int k = 3 + 4 * c;
            float4 q = {sbuf[k], sbuf[k + 1], sbuf[k + 2], sbuf[k + 3]};
            *(float4*)(og + k) = q;
        }
        __syncwarp();
    }

    // one-hot rows (warp-per-row, f2 head/tail + f4 body, coalesced)
    for (int rr = 0; rr < 16; ++rr) {
        const int row = wid * 16 + rr;
        const int idx = idxs[row];
        float* og = out + OFF_ENC + (size_t)(rowBase + row) * 1024;
        if (lane == 0) {
            float2 t = {idx == 0 ? 1.f : 0.f, idx == 1 ? 1.f : 0.f};
            *(float2*)og = t;
        } else if (lane == 1) {
            float2 t = {idx == 1022 ? 1.f : 0.f, idx == 1023 ? 1.f : 0.f};
            *(float2*)(og + 1022) = t;
        }
        #pragma unroll
        for (int c = lane; c < 255; c += 32) {
            int k = 2 + 4 * c;
            float4 v = {0.f, 0.f, 0.f, 0.f};
            unsigned d = (unsigned)(idx - k);
            if (d < 4u) {
                if (d == 0) v.x = 1.f;
                else if (d == 1) v.y = 1.f;
                else if (d == 2) v.z = 1.f;
                else v.w = 1.f;
            }
            *(float4*)(og + k) = v;
        }
    }

    // loss partial reduce + histogram flush
    float* rbuf = (float*)(smem + SM_RBUF);
    rbuf[tid] = psum;
    __syncthreads();
    #pragma unroll
    for (int s = 256; s > 0; s >>= 1) {
        if (tid < s) rbuf[tid] += rbuf[tid + s];
        __syncthreads();
    }
    if (tid == 0) g_part[blockIdx.x] = rbuf[0];
    for (int i = tid; i < NE; i += 512) {
        int h = hist[i];
        if (h) atomicAdd(&g_counts[i], h);
    }
}

// ---------------------------------------------------------------------------
__global__ void vq_finalize(float* __restrict__ out) {
    __shared__ double sd[256];
    int tid = threadIdx.x;
    sd[tid] = (double)g_part[tid];
    __syncthreads();
    #pragma unroll
    for (int st = 128; st > 0; st >>= 1) {
        if (tid < st) sd[tid] += sd[tid + st];
        __syncthreads();
    }
    if (tid == 0) {
        double mean = sd[0] / 16777216.0;
        out[OFF_LOSS] = (float)(mean + 0.25 * mean);
    }
    __syncthreads();
    double h = 0.0;
    for (int i = tid; i < NE; i += 256) {
        double m = (double)g_counts[i] / 65536.0;
        h += m * log(m + 1e-10);
    }
    sd[tid] = h;
    __syncthreads();
    #pragma unroll
    for (int st = 128; st > 0; st >>= 1) {
        if (tid < st) sd[tid] += sd[tid + st];
        __syncthreads();
    }
    if (tid == 0) out[OFF_PERP] = (float)exp(-sd[0]);
}

// ---------------------------------------------------------------------------
extern "C" void kernel_launch(void* const* d_in, const int* in_sizes, int n_in,
                              void* d_out, int out_size) {
    const float* z   = (const float*)d_in[0];
    const float* emb = (const float*)d_in[1];
    float* out = (float*)d_out;

    static int init_done = 0;
    if (!init_done) {
        cudaFuncSetAttribute(vq_main_fused,
                             cudaFuncAttributeMaxDynamicSharedMemorySize, SMEM_TC);
        init_done = 1;
    }

    vq_init<<<1, NE>>>();
    vq_prep<<<128, 256>>>(emb);
    vq_main_fused<<<NROWS / 256, 512, SMEM_TC>>>(z, emb, out);
    vq_finalize<<<1, 256>>>(out);
}

// round 6
// speedup vs baseline: 4.1274x; 1.0052x over previous
#include <cuda_runtime.h>
#include <cuda_bf16.h>
#include <cfloat>
#include <math.h>
#include <stdint.h>

// ---------------------------------------------------------------------------
// VectorQuantizer: z (32,2048,256) f32, emb (1024,256) f32
// Output layout (float32):
//   [0] loss | [1..16777217) z_q | [16777217] perplexity
//   [16777218..+67108864) one-hot | [83886082..+65536) indices
// R6: explicit register double-buffered LDSM/MMA pipeline (volatile asm
// blocked compiler pipelining in R4/R5 -> latency-bound). Rest unchanged.
// ---------------------------------------------------------------------------

#define NROWS   65536
#define CDIM    256
#define NE      1024

#define OFF_LOSS 0LL
#define OFF_ZQ   1LL
#define OFF_PERP 16777217LL
#define OFF_ENC  16777218LL
#define OFF_IDX  83886082LL

#define MARGIN 1.5e-3f

// ----- device scratch -----
__device__ uint4 g_eb4[NE * CDIM / 8];      // emb as bf16 (row-major, 512KB)
__device__ float g_enorm[NE];
__device__ float g_part[256];
__device__ int   g_counts[NE];

// ======================= smem layout (bytes) ===============================
#define RST 528
#define SM_A       0                      // 256*528 = 135168
#define SM_B0      135168                 // 33792
#define SM_B1      168960                 // 33792 (end 202752)
#define SM_EN      202752                 // 4096
#define SM_ZN      206848                 // 1024
#define SM_CNT     207872                 // 16
#define SM_TMP     207888                 // 2048 (znorm partials, later idxs)
#define SMEM_TC    209936
// aliases in dead A region after mainloop:
#define SM_CAND    0                      // 32768
#define SM_LIST    32768                  // 32768
#define SM_ROWRES  65536                  // 2048
#define SM_HIST    67584                  // 4096
#define SM_RBUF    71680                  // 2048
#define SM_SBUF    73728                  // 16 warps * 1KB = 16384

// ======================= PTX helpers =======================================
__device__ __forceinline__ uint32_t smem_u32(const void* p) {
    uint32_t a;
    asm("{ .reg .u64 t; cvta.to.shared.u64 t, %1; cvt.u32.u64 %0, t; }"
        : "=r"(a) : "l"(p));
    return a;
}
#define LDSM_X4(r0, r1, r2, r3, addr) \
    asm volatile("ldmatrix.sync.aligned.m8n8.x4.shared.b16 {%0,%1,%2,%3}, [%4];" \
                 : "=r"(r0), "=r"(r1), "=r"(r2), "=r"(r3) : "r"(addr))
#define MMA16816(c0, c1, c2, c3, a0, a1, a2, a3, b0, b1) \
    asm volatile("mma.sync.aligned.m16n8k16.row.col.f32.bf16.bf16.f32 " \
                 "{%0,%1,%2,%3}, {%4,%5,%6,%7}, {%8,%9}, {%0,%1,%2,%3};" \
                 : "+f"(c0), "+f"(c1), "+f"(c2), "+f"(c3) \
                 : "r"(a0), "r"(a1), "r"(a2), "r"(a3), "r"(b0), "r"(b1))
#define CP16(dst, src) \
    asm volatile("cp.async.cg.shared.global [%0], [%1], 16;" :: "r"(dst), "l"(src))
#define CP_COMMIT() asm volatile("cp.async.commit_group;" ::: "memory")
#define CP_WAIT0()  asm volatile("cp.async.wait_group 0;" ::: "memory")

#define INS2(vv, jj, s, j) do {                                   \
    if ((s) < vv[1]) {                                            \
        if ((s) < vv[0]) { vv[1]=vv[0]; jj[1]=jj[0]; vv[0]=(s); jj[0]=(j); } \
        else             { vv[1]=(s); jj[1]=(j); }                \
    } } while (0)

// load all fragments for one kk into slot s
#define LD_FRAGS(s, kk) do {                                                    \
    LDSM_X4(Af[s][0], Af[s][1], Af[s][2], Af[s][3], aoff + (kk) * 32);          \
    LDSM_X4(Af[s][4], Af[s][5], Af[s][6], Af[s][7], aoff + 16 * RST + (kk) * 32); \
    LDSM_X4(Bf[s][0], Bf[s][1], Bf[s][2], Bf[s][3], Bb + (kk) * 32);            \
    LDSM_X4(Bf[s][4], Bf[s][5], Bf[s][6], Bf[s][7], Bb + 16 * RST + (kk) * 32); \
} while (0)

#define DO_MMAS(s) do {                                                          \
    MMA16816(c[0][0][0], c[0][0][1], c[0][0][2], c[0][0][3],                     \
             Af[s][0], Af[s][1], Af[s][2], Af[s][3], Bf[s][0], Bf[s][1]);        \
    MMA16816(c[0][1][0], c[0][1][1], c[0][1][2], c[0][1][3],                     \
             Af[s][0], Af[s][1], Af[s][2], Af[s][3], Bf[s][2], Bf[s][3]);        \
    MMA16816(c[0][2][0], c[0][2][1], c[0][2][2], c[0][2][3],                     \
             Af[s][0], Af[s][1], Af[s][2], Af[s][3], Bf[s][4], Bf[s][5]);        \
    MMA16816(c[0][3][0], c[0][3][1], c[0][3][2], c[0][3][3],                     \
             Af[s][0], Af[s][1], Af[s][2], Af[s][3], Bf[s][6], Bf[s][7]);        \
    MMA16816(c[1][0][0], c[1][0][1], c[1][0][2], c[1][0][3],                     \
             Af[s][4], Af[s][5], Af[s][6], Af[s][7], Bf[s][0], Bf[s][1]);        \
    MMA16816(c[1][1][0], c[1][1][1], c[1][1][2], c[1][1][3],                     \
             Af[s][4], Af[s][5], Af[s][6], Af[s][7], Bf[s][2], Bf[s][3]);        \
    MMA16816(c[1][2][0], c[1][2][1], c[1][2][2], c[1][2][3],                     \
             Af[s][4], Af[s][5], Af[s][6], Af[s][7], Bf[s][4], Bf[s][5]);        \
    MMA16816(c[1][3][0], c[1][3][1], c[1][3][2], c[1][3][3],                     \
             Af[s][4], Af[s][5], Af[s][6], Af[s][7], Bf[s][6], Bf[s][7]);        \
} while (0)

// ---------------------------------------------------------------------------
// Fused prep: zero histogram + ||e_j||^2 (verbatim R1 rounding) + bf16 pack.
// One warp per code, 1024 warps.
// ---------------------------------------------------------------------------
__global__ void __launch_bounds__(256)
vq_prep(const float* __restrict__ emb) {
    int gw   = (blockIdx.x * blockDim.x + threadIdx.x) >> 5;
    int lane = threadIdx.x & 31;
    const float* e = emb + (size_t)gw * CDIM;
    float s = 0.f;
    #pragma unroll
    for (int i = lane; i < CDIM; i += 32) { float x = e[i]; s += x * x; }
    #pragma unroll
    for (int o = 16; o > 0; o >>= 1) s += __shfl_down_sync(0xffffffffu, s, o);
    if (lane == 0) { g_enorm[gw] = s; g_counts[gw] = 0; }

    const float4* s4 = (const float4*)e;
    float4 a = s4[lane * 2], b = s4[lane * 2 + 1];
    __nv_bfloat162 h0 = __floats2bfloat162_rn(a.x, a.y);
    __nv_bfloat162 h1 = __floats2bfloat162_rn(a.z, a.w);
    __nv_bfloat162 h2 = __floats2bfloat162_rn(b.x, b.y);
    __nv_bfloat162 h3 = __floats2bfloat162_rn(b.z, b.w);
    uint4 pk;
    pk.x = *(uint32_t*)&h0; pk.y = *(uint32_t*)&h1;
    pk.z = *(uint32_t*)&h2; pk.w = *(uint32_t*)&h3;
    g_eb4[(size_t)gw * 32 + lane] = pk;
}

// Prefetch one 64-code bf16 tile into smem (padded rows) via cp.async.
__device__ __forceinline__ void prefetch_B(uint32_t sdst, int ct, int tid) {
    const char* gsrc = (const char*)g_eb4 + (size_t)ct * 64 * 512;
    #pragma unroll
    for (int j = 0; j < 4; ++j) {
        int idx = tid + j * 512;              // 0..2047
        int row = idx >> 5, g = idx & 31;
        CP16(sdst + row * RST + g * 16, gsrc + row * 512 + g * 16);
    }
    CP_COMMIT();
}

// ---------------------------------------------------------------------------
// Fused main: 256 CTAs x 512 threads. CTA = 256 rows x 1024 codes.
// Warp tile 32x32, explicit register-double-buffered ldsm/MMA pipeline.
// ---------------------------------------------------------------------------
__global__ void __launch_bounds__(512, 1)
vq_main_fused(const float* __restrict__ zf, const float* __restrict__ emb,
              float* __restrict__ out) {
    extern __shared__ char smem[];
    const uint32_t sb = smem_u32(smem);
    const int tid = threadIdx.x;
    const int lane = tid & 31, wid = tid >> 5;
    const int mwarp = wid & 7, nwarp = wid >> 3;
    const int rowBase = blockIdx.x * 256;

    prefetch_B(sb + SM_B0, 0, tid);

    float* ens = (float*)(smem + SM_EN);
    float* zns = (float*)(smem + SM_ZN);
    float* tmp = (float*)(smem + SM_TMP);

    for (int i = tid; i < NE; i += 512) ens[i] = g_enorm[i];

    // ---- A tile: load z f32, convert to bf16 (padded smem), norm partials
    {
        int row = tid >> 1, half = tid & 1;
        const float4* zr = (const float4*)zf + ((size_t)(rowBase + row) * 64 + half * 32);
        char* arow = smem + SM_A + row * RST + half * 256;
        float s = 0.f;
        #pragma unroll 4
        for (int j = 0; j < 16; ++j) {
            float4 a = zr[2 * j], b = zr[2 * j + 1];
            s += a.x * a.x; s += a.y * a.y; s += a.z * a.z; s += a.w * a.w;
            s += b.x * b.x; s += b.y * b.y; s += b.z * b.z; s += b.w * b.w;
            __nv_bfloat162 h0 = __floats2bfloat162_rn(a.x, a.y);
            __nv_bfloat162 h1 = __floats2bfloat162_rn(a.z, a.w);
            __nv_bfloat162 h2 = __floats2bfloat162_rn(b.x, b.y);
            __nv_bfloat162 h3 = __floats2bfloat162_rn(b.z, b.w);
            uint4 pk;
            pk.x = *(uint32_t*)&h0; pk.y = *(uint32_t*)&h1;
            pk.z = *(uint32_t*)&h2; pk.w = *(uint32_t*)&h3;
            *(uint4*)(arow + j * 16) = pk;
        }
        tmp[tid] = s;
    }
    __syncthreads();
    if (tid < 256) zns[tid] = tmp[2 * tid] + tmp[2 * tid + 1];
    __syncthreads();

    int rloc[4]; float zn[4];
    #pragma unroll
    for (int rs = 0; rs < 4; ++rs) {
        rloc[rs] = mwarp * 32 + (rs >> 1) * 16 + (rs & 1) * 8 + (lane >> 2);
        zn[rs] = zns[rloc[rs]];
    }

    float bv[4][2]; int bj[4][2];
    #pragma unroll
    for (int rs = 0; rs < 4; ++rs) { bv[rs][0] = bv[rs][1] = FLT_MAX; bj[rs][0] = bj[rs][1] = 0; }

    const uint32_t aoff = sb + SM_A +
        (mwarp * 32 + (lane & 7) + ((lane >> 3) & 1) * 8) * RST + (lane >> 4) * 16;
    const uint32_t boff =
        (nwarp * 32 + (lane & 7) + ((lane >> 4) & 1) * 8) * RST + ((lane >> 3) & 1) * 16;

    for (int ct = 0; ct < 16; ++ct) {
        CP_WAIT0();
        __syncthreads();
        if (ct < 15) prefetch_B(sb + ((ct & 1) ? SM_B0 : SM_B1), ct + 1, tid);
        const uint32_t Bb = ((ct & 1) ? SM_B1 : SM_B0) + sb + boff;

        float c[2][4][4];
        #pragma unroll
        for (int t = 0; t < 2; ++t)
            #pragma unroll
            for (int g = 0; g < 4; ++g)
                #pragma unroll
                for (int q = 0; q < 4; ++q) c[t][g][q] = 0.f;

        // --- register double-buffered pipeline over kk ---
        uint32_t Af[2][8], Bf[2][8];
        LD_FRAGS(0, 0);
        #pragma unroll
        for (int kk = 0; kk < 16; kk += 2) {
            if (kk + 1 < 16) LD_FRAGS(1, kk + 1);
            DO_MMAS(0);
            if (kk + 2 < 16) LD_FRAGS(0, kk + 2);
            DO_MMAS(1);
        }

        #pragma unroll
        for (int t = 0; t < 2; ++t)
            #pragma unroll
            for (int g = 0; g < 4; ++g) {
                const int n0 = ct * 64 + nwarp * 32 + g * 8 + (lane & 3) * 2;
                const float e0 = ens[n0], e1 = ens[n0 + 1];
                const int rsA = t * 2, rsB = t * 2 + 1;
                float s;
                s = fmaf(-2.0f, c[t][g][0], zn[rsA] + e0); INS2(bv[rsA], bj[rsA], s, n0);
                s = fmaf(-2.0f, c[t][g][1], zn[rsA] + e1); INS2(bv[rsA], bj[rsA], s, n0 + 1);
                s = fmaf(-2.0f, c[t][g][2], zn[rsB] + e0); INS2(bv[rsB], bj[rsB], s, n0);
                s = fmaf(-2.0f, c[t][g][3], zn[rsB] + e1); INS2(bv[rsB], bj[rsB], s, n0 + 1);
            }
    }
    __syncthreads();   // all ldsm/A reads done before aliasing A region

    // ---- candidate merge + exact rescore (aliased onto dead A region) -----
    unsigned long long* cand   = (unsigned long long*)(smem + SM_CAND);
    unsigned long long* rowres = (unsigned long long*)(smem + SM_ROWRES);
    int2* list = (int2*)(smem + SM_LIST);
    int*  cnt  = (int*)(smem + SM_CNT);

    if (tid == 0) *cnt = 0;
    #pragma unroll
    for (int rs = 0; rs < 4; ++rs) {
        int slot = (nwarp * 4 + (lane & 3)) * 2;
        cand[rloc[rs] * 16 + slot] =
            ((unsigned long long)__float_as_uint(bv[rs][0]) << 32) | (unsigned)bj[rs][0];
        cand[rloc[rs] * 16 + slot + 1] =
            ((unsigned long long)__float_as_uint(bv[rs][1]) << 32) | (unsigned)bj[rs][1];
    }
    __syncthreads();

    if (tid < 256) {
        unsigned long long best = cand[tid * 16];
        #pragma unroll
        for (int q = 1; q < 16; ++q) {
            unsigned long long e = cand[tid * 16 + q];
            if (e < best) best = e;
        }
        float bvv = __uint_as_float((uint32_t)(best >> 32));
        float thr = bvv + MARGIN;
        int nwithin = 0;
        #pragma unroll
        for (int q = 0; q < 16; ++q) {
            float v = __uint_as_float((uint32_t)(cand[tid * 16 + q] >> 32));
            if (v <= thr) nwithin++;
        }
        if (nwithin <= 1) {
            rowres[tid] = best;
        } else {
            rowres[tid] = 0xFFFFFFFFFFFFFFFFULL;
            #pragma unroll
            for (int q = 0; q < 16; ++q) {
                unsigned long long e = cand[tid * 16 + q];
                float v = __uint_as_float((uint32_t)(e >> 32));
                if (v <= thr) {
                    int p = atomicAdd(cnt, 1);
                    list[p] = make_int2(tid, (int)(e & 0xFFFFFFFFu));
                }
            }
        }
    }
    __syncthreads();

    int nc = *cnt;
    for (int i = tid; i < nc; i += 512) {
        int row = list[i].x, code = list[i].y;
        const float4* zr = (const float4*)(zf + (size_t)(rowBase + row) * CDIM);
        const float4* er = (const float4*)(emb + (size_t)code * CDIM);
        float lo = 0.f, hi = 0.f;
        #pragma unroll 4
        for (int k = 0; k < 64; ++k) {
            float4 a = zr[k], e4 = er[k];
            lo = fmaf(a.x, e4.x, lo);
            hi = fmaf(a.y, e4.y, hi);
            lo = fmaf(a.z, e4.z, lo);
            hi = fmaf(a.w, e4.w, hi);
        }
        float dot = lo + hi;
        float s = (zns[row] + ens[code]) - 2.0f * dot;
        unsigned long long p =
            ((unsigned long long)__float_as_uint(s) << 32) | (unsigned)code;
        atomicMin(&rowres[row], p);
    }
    __syncthreads();

    // ---- finalize indices + fused epilogue ----
    int* idxs = (int*)(smem + SM_TMP);
    int* hist = (int*)(smem + SM_HIST);
    for (int i = tid; i < NE; i += 512) hist[i] = 0;
    __syncthreads();
    if (tid < 256) {
        int wi = (int)(rowres[tid] & 0xFFFFFFFFu);
        idxs[tid] = wi;
        out[OFF_IDX + rowBase + tid] = (float)wi;
        atomicAdd(&hist[wi], 1);
    }
    __syncthreads();

    // z_q + loss (warp-per-row, staged in smem for aligned stores)
    float* sbuf = (float*)(smem + SM_SBUF) + wid * 256;
    float psum = 0.f;
    for (int rr = 0; rr < 16; ++rr) {
        const int row = wid * 16 + rr;
        const int idx = idxs[row];
        const float4* zr4 = (const float4*)zf + (size_t)(rowBase + row) * 64;
        const float4* er4 = (const float4*)emb + (size_t)idx * 64;
        #pragma unroll
        for (int it = 0; it < 2; ++it) {
            int k4 = it * 32 + lane;
            float4 a = zr4[k4], e = er4[k4];
            float dx = e.x - a.x, dy = e.y - a.y, dz = e.z - a.z, dw = e.w - a.w;
            psum += dx * dx + dy * dy + dz * dz + dw * dw;
            float4 q = {a.x + dx, a.y + dy, a.z + dz, a.w + dw};
            *(float4*)&sbuf[k4 * 4] = q;
        }
        __syncwarp();
        float* og = out + OFF_ZQ + (size_t)(rowBase + row) * 256;
        if (lane == 0) og[0] = sbuf[0];
        else if (lane == 1) { float2 t = {sbuf[1], sbuf[2]}; *(float2*)(og + 1) = t; }
        else if (lane == 2) og[255] = sbuf[255];
        #pragma unroll
        for (int c = lane; c < 63; c += 32) {
            int k = 3 + 4 * c;
            float4 q = {sbuf[k], sbuf[k + 1], sbuf[k + 2], sbuf[k + 3]};
            *(float4*)(og + k) = q;
        }
        __syncwarp();
    }

    // one-hot rows (warp-per-row, f2 head/tail + f4 body, coalesced)
    for (int rr = 0; rr < 16; ++rr) {
        const int row = wid * 16 + rr;
        const int idx = idxs[row];
        float* og = out + OFF_ENC + (size_t)(rowBase + row) * 1024;
        if (lane == 0) {
            float2 t = {idx == 0 ? 1.f : 0.f, idx == 1 ? 1.f : 0.f};
            *(float2*)og = t;
        } else if (lane == 1) {
            float2 t = {idx == 1022 ? 1.f : 0.f, idx == 1023 ? 1.f : 0.f};
            *(float2*)(og + 1022) = t;
        }
        #pragma unroll
        for (int c = lane; c < 255; c += 32) {
            int k = 2 + 4 * c;
            float4 v = {0.f, 0.f, 0.f, 0.f};
            unsigned d = (unsigned)(idx - k);
            if (d < 4u) {
                if (d == 0) v.x = 1.f;
                else if (d == 1) v.y = 1.f;
                else if (d == 2) v.z = 1.f;
                else v.w = 1.f;
            }
            *(float4*)(og + k) = v;
        }
    }

    // loss partial reduce + histogram flush
    float* rbuf = (float*)(smem + SM_RBUF);
    rbuf[tid] = psum;
    __syncthreads();
    #pragma unroll
    for (int s = 256; s > 0; s >>= 1) {
        if (tid < s) rbuf[tid] += rbuf[tid + s];
        __syncthreads();
    }
    if (tid == 0) g_part[blockIdx.x] = rbuf[0];
    for (int i = tid; i < NE; i += 512) {
        int h = hist[i];
        if (h) atomicAdd(&g_counts[i], h);
    }
}

// ---------------------------------------------------------------------------
__global__ void vq_finalize(float* __restrict__ out) {
    __shared__ double sd[256];
    int tid = threadIdx.x;
    sd[tid] = (double)g_part[tid];
    __syncthreads();
    #pragma unroll
    for (int st = 128; st > 0; st >>= 1) {
        if (tid < st) sd[tid] += sd[tid + st];
        __syncthreads();
    }
    if (tid == 0) {
        double mean = sd[0] / 16777216.0;
        out[OFF_LOSS] = (float)(mean + 0.25 * mean);
    }
    __syncthreads();
    double h = 0.0;
    for (int i = tid; i < NE; i += 256) {
        double m = (double)g_counts[i] / 65536.0;
        h += m * log(m + 1e-10);
    }
    sd[tid] = h;
    __syncthreads();
    #pragma unroll
    for (int st = 128; st > 0; st >>= 1) {
        if (tid < st) sd[tid] += sd[tid + st];
        __syncthreads();
    }
    if (tid == 0) out[OFF_PERP] = (float)exp(-sd[0]);
}

// ---------------------------------------------------------------------------
extern "C" void kernel_launch(void* const* d_in, const int* in_sizes, int n_in,
                              void* d_out, int out_size) {
    const float* z   = (const float*)d_in[0];
    const float* emb = (const float*)d_in[1];
    float* out = (float*)d_out;

    static int init_done = 0;
    if (!init_done) {
        cudaFuncSetAttribute(vq_main_fused,
                             cudaFuncAttributeMaxDynamicSharedMemorySize, SMEM_TC);
        init_done = 1;
    }

    vq_prep<<<128, 256>>>(emb);
    vq_main_fused<<<NROWS / 256, 512, SMEM_TC>>>(z, emb, out);
    vq_finalize<<<1, 256>>>(out);
}